// round 9
// baseline (speedup 1.0000x reference)
#include <cuda_runtime.h>

#define NN 8192
#define DD 64
#define EK 262144
#define EHK 262144
#define ETOT (EHK + EK)
#define ESPLIT 414208          // edge workers take [0,ESPLIT); matvec blocks take tail ~21%
#define TAB 2048
#define MB 296                 // matvec worker blocks (2 per SM)
#define EB 592                 // edge worker blocks (4 per SM)
#define EWARPS (EB * 8)        // 4736 edge warps
#define MWARPS (MB * 8)        // 2368 matvec-tail warps

// Scratch (device globals: allocation-free)
__device__ float g_sk[NN * DD];   // normalized state_K
__device__ float g_g[NN];         // tanh(state_H)
__device__ float g_fK[NN * DD];   // f_K edge accumulator
__device__ float g_fHa[NN];       // f_H edge accumulator
__device__ float g_tab[TAB + 1];  // dE(s) lookup table, s in [-1,1]

// No "memory" clobber: g_fK/g_fHa are write-only in mega; lets ptxas pipeline
// the next iteration's loads past this red.
__device__ __forceinline__ void red4(float* p, float a, float b, float c, float d) {
    asm volatile("red.global.add.v4.f32 [%0], {%1,%2,%3,%4};"
                 :: "l"(p), "f"(a), "f"(b), "f"(c), "f"(d));
}
__device__ __forceinline__ void red1(float* p, float a) {
    asm volatile("red.global.add.f32 [%0], %1;" :: "l"(p), "f"(a));
}

__device__ __forceinline__ float warp_sum(float v) {
    #pragma unroll
    for (int o = 16; o; o >>= 1) v += __shfl_xor_sync(0xFFFFFFFFu, v, o);
    return v;
}

// --- prep: normalize state_K rows, g=tanh(sH), zero accumulators, build table.
//     Table built warp-per-entry (2 tanh/lane) by blocks 0..128.
__global__ void prep_kernel(const float* __restrict__ sH, const float* __restrict__ sK,
                            const float* __restrict__ w1, const float* __restrict__ b1,
                            const float* __restrict__ w2) {
    int warp = threadIdx.x >> 5, lane = threadIdx.x & 31;
    int row = blockIdx.x * 8 + warp;
    float2 v = ((const float2*)(sK + row * DD))[lane];
    float ss = warp_sum(v.x * v.x + v.y * v.y);
    float inv = rsqrtf(ss);
    ((float2*)(g_sk + row * DD))[lane] = make_float2(v.x * inv, v.y * inv);
    if (lane == 0) g_g[row] = tanhf(sH[row]);

    int gt = blockIdx.x * 256 + threadIdx.x;          // 0..262143
    if (gt < NN * DD / 4) ((float4*)g_fK)[gt] = make_float4(0.f, 0.f, 0.f, 0.f);
    if (gt < NN / 4)      ((float4*)g_fHa)[gt] = make_float4(0.f, 0.f, 0.f, 0.f);

    int entry = blockIdx.x * 8 + warp;                // warp-per-table-entry
    if (entry <= TAB) {
        float s = entry * (2.0f / TAB) - 1.0f;
        float a0 = tanhf(s * __ldg(w1 + lane)      + __ldg(b1 + lane))      * __ldg(w2 + lane);
        float a1 = tanhf(s * __ldg(w1 + lane + 32) + __ldg(b1 + lane + 32)) * __ldg(w2 + lane + 32);
        float acc = warp_sum(a0 + a1);
        if (lane == 0) g_tab[entry] = acc;
    }
}

// edge body: warp-per-edge, half-warp per endpoint.
__device__ __forceinline__ void do_edge(int e, int lane,
                                        const int* __restrict__ indK,
                                        const int* __restrict__ indHK) {
    int c = lane & 15;                    // float4 chunk within row
    bool isHK = e < EHK;
    int2 ij = isHK ? __ldg((const int2*)indHK + e)
                   : __ldg((const int2*)indK + (e - EHK));
    int myRow = (lane < 16) ? ij.x : ij.y;
    float4 v = __ldg((const float4*)(g_sk + myRow * DD) + c);
    float4 w;                              // partner row chunk
    w.x = __shfl_xor_sync(0xFFFFFFFFu, v.x, 16);
    w.y = __shfl_xor_sync(0xFFFFFFFFu, v.y, 16);
    w.z = __shfl_xor_sync(0xFFFFFFFFu, v.z, 16);
    w.w = __shfl_xor_sync(0xFFFFFFFFu, v.w, 16);
    float d = v.x * w.x + v.y * w.y + v.z * w.z + v.w * w.w;
    d += __shfl_xor_sync(0xFFFFFFFFu, d, 1);
    d += __shfl_xor_sync(0xFFFFFFFFu, d, 2);
    d += __shfl_xor_sync(0xFFFFFFFFu, d, 4);
    d += __shfl_xor_sync(0xFFFFFFFFu, d, 8);   // s = <row_i, row_j>
    float coef;
    if (isHK) {
        float gm = __ldg(g_g + myRow);
        float gp = __shfl_xor_sync(0xFFFFFFFFu, gm, 16);
        if ((lane & 15) == 0)                       // lanes 0 and 16
            red1(g_fHa + myRow, d * gp * 0.5f);     // /KAPPA_H
        coef = -0.5f * gm * gp;                     // -G/KAPPA_K
    } else {
        float t = (fminf(fmaxf(d, -1.f), 1.f) + 1.f) * (TAB * 0.5f);
        int i0 = min((int)t, TAB - 1);
        float f = t - (float)i0;
        float t0 = __ldg(g_tab + i0), t1 = __ldg(g_tab + i0 + 1);
        coef = t0 + (t1 - t0) * f;                  // dE(s)
    }
    red4(g_fK + myRow * DD + c * 4, coef * w.x, coef * w.y, coef * w.z, coef * w.w);
}

// --- mega: persistent workers. Blocks 0..MB-1: matvec rows, then edge tail.
//     Blocks MB..MB+EB-1: edges [0, ESPLIT).
__global__ __launch_bounds__(256, 6) void mega_kernel(
    const float* __restrict__ sH, const float* __restrict__ W,
    const int* __restrict__ indK, const int* __restrict__ indHK,
    float* __restrict__ out)
{
    int lane = threadIdx.x & 31, warp = threadIdx.x >> 5;

    if (blockIdx.x < MB) {
        // ---- matvec worker: rows blockIdx.x, +MB, ... keeps DRAM saturated.
        __shared__ float rr[8];
        const float4* g4 = (const float4*)g_g;
        for (int row = blockIdx.x; row < NN; row += MB) {
            const float4* Wr = (const float4*)(W + (size_t)row * NN);
            float acc = 0.f;
            #pragma unroll
            for (int it = 0; it < 8; it++) {
                int k = threadIdx.x + it * 256;
                float4 w = __ldcs(Wr + k);     // stream: don't pollute L2
                float4 g = g4[k];
                acc += w.x * g.x + w.y * g.y + w.z * g.z + w.w * g.w;
            }
            acc = warp_sum(acc);
            if (lane == 0) rr[warp] = acc;
            __syncthreads();
            if (threadIdx.x == 0) {
                float v = rr[0] + rr[1] + rr[2] + rr[3] + rr[4] + rr[5] + rr[6] + rr[7];
                out[row] = -sH[row] + v;
            }
            __syncthreads();
        }
        // ---- then help with the edge tail [ESPLIT, ETOT)
        int wg = blockIdx.x * 8 + warp;
        #pragma unroll 2
        for (int e = ESPLIT + wg; e < ETOT; e += MWARPS)
            do_edge(e, lane, indK, indHK);
        return;
    }

    // ---- edge worker: edges [0, ESPLIT)
    int wg = (blockIdx.x - MB) * 8 + warp;
    #pragma unroll 2
    for (int e = wg; e < ESPLIT; e += EWARPS)
        do_edge(e, lane, indK, indHK);
}

// --- finalize: f_H += fHacc; f_K = -acc + sk*<sk,acc> + sk @ (omega-omega^T)/2.
__global__ void fin_kernel(const float* __restrict__ omega, float* __restrict__ out) {
    __shared__ float A[DD * DD];      // antisymmetrized omega
    __shared__ float srow[8 * DD];
    for (int k = threadIdx.x; k < DD * DD; k += 256) {
        int rI = k >> 6, cc = k & 63;
        A[k] = 0.5f * (omega[k] - omega[cc * DD + rI]);
    }
    __syncthreads();
    int warp = threadIdx.x >> 5, lane = threadIdx.x & 31;
    int row = blockIdx.x * 8 + warp;
    if (lane == 0) out[row] += g_fHa[row];            // finish f_H
    float2 skv = ((const float2*)(g_sk + row * DD))[lane];
    float2 fv  = ((const float2*)(g_fK + row * DD))[lane];
    float d = warp_sum(skv.x * fv.x + skv.y * fv.y);
    ((float2*)(srow + warp * DD))[lane] = skv;
    __syncwarp();
    const float* sr = srow + warp * DD;
    const float2* A2 = (const float2*)A;
    float m0 = 0.f, m1 = 0.f;
    #pragma unroll
    for (int k = 0; k < DD; k++) {
        float sv = sr[k];
        float2 av = A2[k * 32 + lane];
        m0 += sv * av.x;
        m1 += sv * av.y;
    }
    float o0 = -fv.x + skv.x * d + m0;
    float o1 = -fv.y + skv.y * d + m1;
    ((float2*)(out + NN + row * DD))[lane] = make_float2(o0, o1);
}

extern "C" void kernel_launch(void* const* d_in, const int* in_sizes, int n_in,
                              void* d_out, int out_size) {
    const float* sH   = (const float*)d_in[0];
    const float* sK   = (const float*)d_in[1];
    const float* WH   = (const float*)d_in[2];
    const float* om   = (const float*)d_in[3];
    const float* w1   = (const float*)d_in[4];
    const float* b1   = (const float*)d_in[5];
    const float* w2   = (const float*)d_in[6];
    const int*  indK  = (const int*)d_in[7];
    const int*  indHK = (const int*)d_in[8];
    float* out = (float*)d_out;

    prep_kernel<<<NN / 8, 256>>>(sH, sK, w1, b1, w2);
    mega_kernel<<<MB + EB, 256>>>(sH, WH, indK, indHK, out);
    fin_kernel<<<NN / 8, 256>>>(om, out);
}